// round 11
// baseline (speedup 1.0000x reference)
#include <cuda_runtime.h>
#include <math.h>

typedef unsigned long long ull;

#define NDIM 512
#define DDIM 784
#define CDIM 10
#define ITERS 40
#define QMAX 127.0f

#define MT 8          // row tiles (64 rows each) == cluster size
#define NT 16         // column groups (8 cols each)
#define GRID (MT*NT)  // 128 CTAs
#define TPB 512
#define ZSTR 12       // padded z row stride (8 used + 4 pad)

// shared layout (float offsets)
#define S_Z    0          // 512*12 = 6144 (single buffer, per-warp row ownership)
#define S_RED  6144       // 16 warps * 640 (lane*20: 16 floats + 4 pad) = 10240
#define S_UX   16384      // 512
#define S_SCR  16896      // 16 (cluster max-combine scratch)
#define S_MB   16912      // 2 (8-byte mbarrier)
#define SMEM_FLOATS 16928
#define SMEM_BYTES (SMEM_FLOATS*4)
// Phase B scratch overlaps S_Z/S_RED: xs @0 (6272), uq @6272 (7424, ends 13696)

// ---- device globals (z ping-pong through L2; proven data path) ----
__device__ float g_zA[NDIM*128];
__device__ float g_zB[NDIM*128];

// -------- cluster helpers --------
__device__ __forceinline__ unsigned smem_u32(const void* p){
    unsigned r; asm("{.reg .u64 t; cvta.to.shared.u64 t, %1; cvt.u32.u64 %0, t;}" : "=r"(r) : "l"(p)); return r;
}
__device__ __forceinline__ float ldc_f32(unsigned local_addr, unsigned rank){
    float v;
    asm volatile("{.reg .b32 ra; mapa.shared::cluster.u32 ra, %1, %2;\n\t"
                 "ld.shared::cluster.f32 %0, [ra];}"
                 : "=f"(v) : "r"(local_addr), "r"(rank));
    return v;
}
__device__ __forceinline__ void mbar_init(unsigned mb, unsigned cnt){
    asm volatile("mbarrier.init.shared.b64 [%0], %1;" :: "r"(mb), "r"(cnt) : "memory");
}
__device__ __forceinline__ void mbar_arrive_self(unsigned mb){
    asm volatile("mbarrier.arrive.shared.b64 _, [%0];" :: "r"(mb) : "memory");
}
__device__ __forceinline__ void mbar_arrive_rank(unsigned mb, unsigned rank){
    asm volatile("{.reg .b32 ra; mapa.shared::cluster.u32 ra, %0, %1;\n\t"
                 "mbarrier.arrive.shared::cluster.b64 _, [ra];}"
                 :: "r"(mb), "r"(rank) : "memory");
}
__device__ __forceinline__ void mbar_wait_parity(unsigned mb, unsigned parity){
    unsigned done;
    asm volatile("{\n\t.reg .pred p;\n\t"
                 "mbarrier.try_wait.parity.shared.b64 p, [%1], %2;\n\t"
                 "selp.b32 %0, 1, 0, p;\n\t}"
                 : "=r"(done) : "r"(mb), "r"(parity) : "memory");
    if (!done) {
        asm volatile("{\n\t.reg .pred P1;\n\t"
                     "WL_%=:\n\t"
                     "mbarrier.try_wait.parity.shared.b64 P1, [%0], %1, 0x989680;\n\t"
                     "@P1 bra.uni WD_%=;\n\t"
                     "bra.uni WL_%=;\n\t"
                     "WD_%=:\n\t}"
                     :: "r"(mb), "r"(parity) : "memory");
    }
}
#define CLUSTER_SYNC_() do{ \
    asm volatile("barrier.cluster.arrive.aligned;" ::: "memory"); \
    asm volatile("barrier.cluster.wait.aligned;"   ::: "memory"); }while(0)

// -------- f32x2 helpers --------
__device__ __forceinline__ ull pk2(float x){
    ull d; asm("mov.b64 %0, {%1,%1};" : "=l"(d) : "r"(__float_as_uint(x))); return d;
}
__device__ __forceinline__ void fma2(ull& d, ull a, ull b){
    asm("fma.rn.f32x2 %0, %1, %2, %3;" : "=l"(d) : "l"(a), "l"(b), "l"(d));
}
__device__ __forceinline__ float warpmax(float v){
    #pragma unroll
    for (int o = 16; o; o >>= 1) v = fmaxf(v, __shfl_xor_sync(0xffffffffu, v, o));
    return v;
}

extern "C" __global__ void __launch_bounds__(TPB, 1) __cluster_dims__(MT, 1, 1)
mondeq_kernel(const float* __restrict__ W, const float* __restrict__ U,
              const float* __restrict__ bvec, const float* __restrict__ x,
              const float* __restrict__ Wc, const float* __restrict__ bcv,
              float* __restrict__ out)
{
    extern __shared__ float sm[];
    float* sZ   = sm + S_Z;
    float* sRed = sm + S_RED;
    float* sUx  = sm + S_UX;
    float* scr  = sm + S_SCR;

    const int tid  = threadIdx.x;
    unsigned mi_u; asm("mov.u32 %0, %%cluster_ctarank;" : "=r"(mi_u));
    const int mi   = (int)mi_u;        // row tile 0..7 (cluster rank)
    const int nj   = blockIdx.x >> 3;  // column group 0..15
    const int wid  = tid >> 5;         // warp: k within tile = wid*4 + j2
    const int lane = tid & 31;         // rows 2*lane, 2*lane+1 of own tile
    const unsigned smb = smem_u32(sm);
    const unsigned mb  = smb + S_MB*4;
    const unsigned scrb = smb + S_SCR*4;

    // ================= Phase A: maxes (cluster-local) + mbarrier init ==============
    {
        float lw = 0.f, lu = 0.f, lb = 0.f;
        const float4* W4 = (const float4*)(W + (size_t)(mi*64)*NDIM);
        for (int i = tid; i < 64*NDIM/4; i += TPB) {
            float4 v = W4[i];
            lw = fmaxf(lw, fmaxf(fmaxf(fabsf(v.x),fabsf(v.y)), fmaxf(fabsf(v.z),fabsf(v.w))));
        }
        const float4* U4 = (const float4*)(U + (size_t)(mi*64)*DDIM);
        for (int i = tid; i < 64*DDIM/4; i += TPB) {
            float4 v = U4[i];
            lu = fmaxf(lu, fmaxf(fmaxf(fabsf(v.x),fabsf(v.y)), fmaxf(fabsf(v.z),fabsf(v.w))));
        }
        lb = fabsf(bvec[tid]);          // 512 threads cover all 512
        lw = warpmax(lw); lu = warpmax(lu); lb = warpmax(lb);
        if (lane == 0) { sm[wid] = lw; sm[16 + wid] = lu; sm[32 + wid] = lb; }
        __syncthreads();
        if (tid == 0) {
            float mw = 0.f, mu = 0.f, mb2 = 0.f;
            #pragma unroll
            for (int i = 0; i < 16; ++i) {
                mw = fmaxf(mw, sm[i]); mu = fmaxf(mu, sm[16+i]); mb2 = fmaxf(mb2, sm[32+i]);
            }
            scr[0] = mw; scr[1] = mu; scr[2] = mb2;
            mbar_init(mb, MT);          // 8 arrivals per generation
        }
        __syncthreads();
    }
    CLUSTER_SYNC_();                    // scr + mbarrier init visible cluster-wide
    if (tid == 0) {
        float mw = 0.f, mu = 0.f;
        #pragma unroll
        for (unsigned r = 0; r < MT; ++r) {
            mw = fmaxf(mw, ldc_f32(scrb,     r));
            mu = fmaxf(mu, ldc_f32(scrb + 4, r));
        }
        scr[4] = mw; scr[5] = mu;
    }
    __syncthreads();
    const float scW = scr[4]   / QMAX;
    const float scU = scr[5]   / QMAX;
    const float scB = scr[2]   / QMAX;   // b max is already CTA-complete
    __syncthreads();                     // scr reads done before Phase B overwrites low smem

    // ================= Phase B (group-local): Ux = Uq @ x^T + bq ===================
    {
        float* xs = sm;            // [784][8] transposed x cols (6272)
        float* uq = sm + 6272;     // [64][116] quantized U chunk (7424, ends 13696)
        const int r = tid >> 3;
        const int c = tid & 7;
        for (int i = tid; i < DDIM*8; i += TPB) {
            const int k = i >> 3, cc = i & 7;
            xs[i] = x[(size_t)(nj*8 + cc)*DDIM + k];
        }
        float acc = 0.f;
        for (int ch = 0; ch < 7; ++ch) {
            __syncthreads();
            for (int i = tid; i < 64*112; i += TPB) {
                const int rr = i / 112, kk = i - rr*112;
                uq[rr*116 + kk] = rintf(U[(size_t)(mi*64 + rr)*DDIM + ch*112 + kk] / scU) * scU;
            }
            __syncthreads();
            const float* up = uq + r*116;
            const float* xp = xs + ch*112*8 + c;
            #pragma unroll 4
            for (int kk = 0; kk < 112; ++kk)
                acc = fmaf(up[kk], xp[kk*8], acc);
        }
        const float bq = rintf(bvec[mi*64 + r] / scB) * scB;
        __syncthreads();
        sUx[tid] = acc + bq;
    }

    // ================= Phase C: quantized W -> per-thread scalar registers =========
    float w0[32], w1[32];
    {
        const float* Wr0 = W + (size_t)(mi*64 + 2*lane)*NDIM;
        const float* Wr1 = Wr0 + NDIM;
        #pragma unroll
        for (int t = 0; t < 8; ++t) {
            const int k0 = t*64 + wid*4;
            const float4 a = *(const float4*)(Wr0 + k0);
            const float4 b = *(const float4*)(Wr1 + k0);
            w0[t*4+0] = rintf(a.x/scW)*scW; w0[t*4+1] = rintf(a.y/scW)*scW;
            w0[t*4+2] = rintf(a.z/scW)*scW; w0[t*4+3] = rintf(a.w/scW)*scW;
            w1[t*4+0] = rintf(b.x/scW)*scW; w1[t*4+1] = rintf(b.y/scW)*scW;
            w1[t*4+2] = rintf(b.z/scW)*scW; w1[t*4+3] = rintf(b.w/scW)*scW;
        }
    }

    // ================= z1 = relu(0.5*Ux): local own rows + publish + arrive ========
    {
        const float z1 = fmaxf(0.5f * sUx[tid], 0.f);
        sZ[(mi*64 + (tid>>3))*ZSTR + (tid&7)] = z1;
        __stcg(&g_zA[nj*4096 + mi*512 + tid], z1);
    }
    __syncthreads();
    if (tid == 0) {
        asm volatile("fence.acq_rel.gpu;" ::: "memory");
        mbar_arrive_self(mb);
        #pragma unroll
        for (int p = 1; p < 8; ++p) mbar_arrive_rank(mb, (unsigned)((mi + p) & 7));
    }
    float* gz_cur = g_zA;
    float* gz_nxt = g_zB;

    // per-warp staging assignment: lane < 28 stages one remote row it will consume
    int st_row = -1;
    if (lane < 28) {
        int t = lane >> 2; t += (t >= mi);
        st_row = t*64 + wid*4 + (lane & 3);
    }

    // ================= Main loop: 39 iterations (z2..z40) ==========================
    for (int it = 2; it <= ITERS; ++it) {
        ull a00=0,a01=0,a02=0,a03=0, a10=0,a11=0,a12=0,a13=0;

        // ---- own-tile GEMM first (local rows current; overlaps peers' arrivals) ----
        {
            const float* zt = sZ + (mi*64 + wid*4)*ZSTR;
            #pragma unroll
            for (int j2 = 0; j2 < 4; ++j2) {
                const float* q = zt + j2*ZSTR;
                const ulonglong2 zA = *(const ulonglong2*)(q);
                const ulonglong2 zB = *(const ulonglong2*)(q + 4);
                const ull wd0 = pk2(w0[mi*4+j2]);
                const ull wd1 = pk2(w1[mi*4+j2]);
                fma2(a00, wd0, zA.x); fma2(a01, wd0, zA.y);
                fma2(a02, wd0, zB.x); fma2(a03, wd0, zB.y);
                fma2(a10, wd1, zA.x); fma2(a11, wd1, zA.y);
                fma2(a12, wd1, zB.x); fma2(a13, wd1, zB.y);
            }
        }

        // ---- per-warp local mbarrier wake (gen it-1), then stage own remote rows ---
        if (lane == 0) mbar_wait_parity(mb, (unsigned)((it - 2) & 1));
        __syncwarp();
        if (lane < 28) {
            const float* src = gz_cur + nj*4096 + st_row*8;
            const float4 a = __ldcg((const float4*)src);
            const float4 b = __ldcg((const float4*)(src + 4));
            *(float4*)(sZ + st_row*ZSTR)     = a;
            *(float4*)(sZ + st_row*ZSTR + 4) = b;
        }
        __syncwarp();

        // ---- GEMM over the 7 remote tiles ----
        #pragma unroll
        for (int t = 0; t < 8; ++t) {
            if (t == mi) continue;
            const float* zt = sZ + (t*64 + wid*4)*ZSTR;
            #pragma unroll
            for (int j2 = 0; j2 < 4; ++j2) {
                const float* q = zt + j2*ZSTR;
                const ulonglong2 zA = *(const ulonglong2*)(q);
                const ulonglong2 zB = *(const ulonglong2*)(q + 4);
                const ull wd0 = pk2(w0[t*4+j2]);
                const ull wd1 = pk2(w1[t*4+j2]);
                fma2(a00, wd0, zA.x); fma2(a01, wd0, zA.y);
                fma2(a02, wd0, zB.x); fma2(a03, wd0, zB.y);
                fma2(a10, wd1, zA.x); fma2(a11, wd1, zA.y);
                fma2(a12, wd1, zB.x); fma2(a13, wd1, zB.y);
            }
        }

        // ---- partials: sRed[wid*640 + lane*20 + {0..15}] ----
        {
            float* rp = sRed + wid*640 + lane*20;
            ulonglong2 s0; s0.x = a00; s0.y = a01; *(ulonglong2*)(rp)      = s0;
            ulonglong2 s1; s1.x = a02; s1.y = a03; *(ulonglong2*)(rp + 4)  = s1;
            ulonglong2 s2; s2.x = a10; s2.y = a11; *(ulonglong2*)(rp + 8)  = s2;
            ulonglong2 s3; s3.x = a12; s3.y = a13; *(ulonglong2*)(rp + 12) = s3;
        }
        __syncthreads();

        // ---- combine + relu + publish + refresh local own row ----
        {
            const int coff = (tid >> 4)*20 + ((tid >> 3) & 1)*8 + (tid & 7);
            float s = 0.f;
            const float* rq = sRed + coff;
            #pragma unroll
            for (int q = 0; q < 16; ++q) s += rq[q*640];
            const int zidx = (mi*64 + (tid >> 3))*ZSTR + (tid & 7);
            const float u  = sUx[tid];
            const float zo = sZ[zidx];
            const float v  = fmaf(0.5f, zo, 0.5f * (s + u));
            const float zn = fmaxf(v, 0.f);
            __stcg(&gz_nxt[nj*4096 + mi*512 + tid], zn);
            sZ[zidx] = zn;
        }
        __syncthreads();
        if (tid == 0) {
            asm volatile("fence.acq_rel.gpu;" ::: "memory");
            mbar_arrive_self(mb);
            #pragma unroll
            for (int p = 1; p < 8; ++p) mbar_arrive_rank(mb, (unsigned)((mi + p) & 7));
        }

        { float* t = gz_cur; gz_cur = gz_nxt; gz_nxt = t; }
    }

    // ---- terminal: observe gen 40 (also guarantees all arrives landed) ----
    if (lane == 0) mbar_wait_parity(mb, (unsigned)((ITERS - 1) & 1));
    __syncwarp();
    __syncthreads();

    // ================= Classifier (rank 0 of each cluster) =========================
    if (mi == 0 && tid < 8*CDIM) {
        const int bl = tid / CDIM, cc = tid - bl*CDIM;
        const float* zp = gz_cur + nj*4096 + bl;
        const float* wc = Wc + cc*NDIM;
        float acc = bcv[cc];
        #pragma unroll 8
        for (int n = 0; n < NDIM; ++n)
            acc = fmaf(__ldcg(zp + n*8), wc[n], acc);
        out[(nj*8 + bl)*CDIM + cc] = acc;
    }
}

extern "C" void kernel_launch(void* const* d_in, const int* in_sizes, int n_in,
                              void* d_out, int out_size) {
    (void)in_sizes; (void)n_in; (void)out_size;
    cudaFuncSetAttribute(mondeq_kernel, cudaFuncAttributeMaxDynamicSharedMemorySize, SMEM_BYTES);
    mondeq_kernel<<<GRID, TPB, SMEM_BYTES>>>(
        (const float*)d_in[0],   // W  (512,512)
        (const float*)d_in[1],   // U  (512,784)
        (const float*)d_in[2],   // b  (512)
        (const float*)d_in[3],   // x  (128,784)
        (const float*)d_in[4],   // Wc (10,512)
        (const float*)d_in[5],   // bc (10)
        (float*)d_out);          // logits (128,10)
}

// round 12
// speedup vs baseline: 2.2123x; 2.2123x over previous
#include <cuda_runtime.h>
#include <math.h>

typedef unsigned long long ull;

#define NDIM 512
#define DDIM 784
#define CDIM 10
#define ITERS 40
#define QMAX 127.0f

#define MT 8          // row tiles (64 rows each)
#define NT 16         // column groups (8 cols each)
#define GRID (MT*NT)  // 128 CTAs
#define TPB 512
#define ZSTR 12       // padded z row stride (8 used + 4 pad)

// shared layout (float offsets)
#define S_Z    0          // 512*12 = 6144 (single buffer, per-warp row ownership)
#define S_RED  6144       // 16 warps * 640 (lane*20: 16 floats + 4 pad) = 10240
#define S_UX   16384      // 512
#define S_TOK  16896      // token word
#define SMEM_FLOATS 16928
#define SMEM_BYTES (SMEM_FLOATS*4)
// Phase B scratch overlaps S_Z/S_RED: xs @0 (6272), uq @6272 (7424, ends 13696)

// ---- device globals (scratch) ----
__device__ float g_zA[NDIM*128];
__device__ float g_zB[NDIM*128];
__device__ unsigned g_maxW, g_maxU, g_maxB;        // idempotent atomicMax
__device__ unsigned g_gcnt, g_ggen;                // grid barrier (used once)
__device__ unsigned g_flag[NT*8*32];               // per-CTA flags, 128B apart

// -------- grid barrier (prologue only) --------
__device__ __forceinline__ void gbar(unsigned* cnt, unsigned* gen, unsigned expected) {
    __syncthreads();
    if (threadIdx.x == 0) {
        unsigned snap, t;
        asm volatile("ld.acquire.gpu.global.u32 %0, [%1];" : "=r"(snap) : "l"(gen) : "memory");
        asm volatile("atom.acq_rel.gpu.global.add.u32 %0, [%1], %2;"
                     : "=r"(t) : "l"(cnt), "r"(1u) : "memory");
        if (t == expected - 1u) {
            asm volatile("st.relaxed.gpu.global.u32 [%0], %1;" :: "l"(cnt), "r"(0u) : "memory");
            asm volatile("red.release.gpu.global.add.u32 [%0], %1;" :: "l"(gen), "r"(1u) : "memory");
        } else {
            unsigned g;
            do {
                asm volatile("ld.acquire.gpu.global.u32 %0, [%1];" : "=r"(g) : "l"(gen) : "memory");
            } while (g == snap);
        }
    }
    __syncthreads();
}

// -------- flag / token primitives --------
__device__ __forceinline__ void flag_store(unsigned* f, unsigned v) {
    asm volatile("st.release.gpu.global.u32 [%0], %1;" :: "l"(f), "r"(v) : "memory");
}
__device__ __forceinline__ unsigned flag_ld(const unsigned* f) {
    unsigned v;
    asm volatile("ld.relaxed.gpu.global.u32 %0, [%1];" : "=r"(v) : "l"(f) : "memory");
    return v;
}
__device__ __forceinline__ unsigned flag_acq(const unsigned* f) {
    unsigned v;
    asm volatile("ld.acquire.gpu.global.u32 %0, [%1];" : "=r"(v) : "l"(f) : "memory");
    return v;
}
__device__ __forceinline__ unsigned smem_u32(const void* p){
    unsigned r; asm("{.reg .u64 t; cvta.to.shared.u64 t, %1; cvt.u32.u64 %0, t;}" : "=r"(r) : "l"(p)); return r;
}
__device__ __forceinline__ void tok_store(unsigned a, unsigned v){
    asm volatile("st.release.cta.shared.u32 [%0], %1;" :: "r"(a), "r"(v) : "memory");
}
__device__ __forceinline__ unsigned tok_load(unsigned a){
    unsigned v;
    asm volatile("ld.acquire.cta.shared.u32 %0, [%1];" : "=r"(v) : "r"(a) : "memory");
    return v;
}

// -------- f32x2 helpers --------
__device__ __forceinline__ ull pk2(float x){
    ull d; asm("mov.b64 %0, {%1,%1};" : "=l"(d) : "r"(__float_as_uint(x))); return d;
}
__device__ __forceinline__ void fma2(ull& d, ull a, ull b){
    asm("fma.rn.f32x2 %0, %1, %2, %3;" : "=l"(d) : "l"(a), "l"(b), "l"(d));
}
__device__ __forceinline__ float warpmax(float v){
    #pragma unroll
    for (int o = 16; o; o >>= 1) v = fmaxf(v, __shfl_xor_sync(0xffffffffu, v, o));
    return v;
}

extern "C" __global__ void __launch_bounds__(TPB, 1)
mondeq_kernel(const float* __restrict__ W, const float* __restrict__ U,
              const float* __restrict__ bvec, const float* __restrict__ x,
              const float* __restrict__ Wc, const float* __restrict__ bcv,
              float* __restrict__ out)
{
    extern __shared__ float sm[];
    float* sZ   = sm + S_Z;
    float* sRed = sm + S_RED;
    float* sUx  = sm + S_UX;

    const int tid  = threadIdx.x;
    const int cta  = blockIdx.x;
    const int mi   = cta & (MT - 1);   // row tile 0..7
    const int nj   = cta >> 3;         // column group 0..15
    const int wid  = tid >> 5;         // warp: k within tile = wid*4 + j2
    const int lane = tid & 31;         // rows 2*lane, 2*lane+1 of own tile
    unsigned* fg   = &g_flag[nj*8*32]; // group flag base
    unsigned* fown = fg + mi*32;
    const unsigned tok = smem_u32(sm) + S_TOK*4;

    // base generation (own flag written only by this CTA; stable at launch)
    unsigned base = 0u;
    if (tid == 0) base = flag_ld(fown);

    // ================= Phase A: per-tensor max|.| (idempotent atomicMax) ==========
    {
        float lw = 0.f, lu = 0.f, lb = 0.f;
        const int gid = cta * TPB + tid;
        for (int i = gid; i < NDIM*NDIM; i += GRID*TPB) lw = fmaxf(lw, fabsf(W[i]));
        for (int i = gid; i < NDIM*DDIM; i += GRID*TPB) lu = fmaxf(lu, fabsf(U[i]));
        if (gid < NDIM) lb = fabsf(bvec[gid]);
        lw = warpmax(lw); lu = warpmax(lu); lb = warpmax(lb);
        if (lane == 0) { sm[wid] = lw; sm[16 + wid] = lu; sm[32 + wid] = lb; }
        __syncthreads();
        if (tid == 0) {
            float mw = 0.f, mu = 0.f, mb = 0.f;
            #pragma unroll
            for (int i = 0; i < 16; ++i) {
                mw = fmaxf(mw, sm[i]); mu = fmaxf(mu, sm[16+i]); mb = fmaxf(mb, sm[32+i]);
            }
            atomicMax(&g_maxW, __float_as_uint(mw));
            atomicMax(&g_maxU, __float_as_uint(mu));
            atomicMax(&g_maxB, __float_as_uint(mb));
            ((unsigned*)sm)[S_TOK] = 0u;    // token init
        }
    }
    gbar(&g_gcnt, &g_ggen, GRID);   // the ONLY grid barrier

    const float scW = __uint_as_float(__ldcg(&g_maxW)) / QMAX;
    const float scU = __uint_as_float(__ldcg(&g_maxU)) / QMAX;
    const float scB = __uint_as_float(__ldcg(&g_maxB)) / QMAX;

    // ================= Phase B (group-local): Ux = Uq @ x^T + bq ===================
    {
        float* xs = sm;            // [784][8] transposed x cols (6272)
        float* uq = sm + 6272;     // [64][116] quantized U chunk (7424)
        const int r = tid >> 3;
        const int c = tid & 7;
        for (int i = tid; i < DDIM*8; i += TPB) {
            const int k = i >> 3, cc = i & 7;
            xs[i] = x[(size_t)(nj*8 + cc)*DDIM + k];
        }
        float acc = 0.f;
        for (int ch = 0; ch < 7; ++ch) {
            __syncthreads();
            for (int i = tid; i < 64*112; i += TPB) {
                const int rr = i / 112, kk = i - rr*112;
                uq[rr*116 + kk] = rintf(U[(size_t)(mi*64 + rr)*DDIM + ch*112 + kk] / scU) * scU;
            }
            __syncthreads();
            const float* up = uq + r*116;
            const float* xp = xs + ch*112*8 + c;
            #pragma unroll 4
            for (int kk = 0; kk < 112; ++kk)
                acc = fmaf(up[kk], xp[kk*8], acc);
        }
        const float bq = rintf(bvec[mi*64 + r] / scB) * scB;
        __syncthreads();                 // uq/xs reads done before sZ/sRed reuse
        sUx[tid] = acc + bq;
    }

    // ================= Phase C: quantized W -> per-thread scalar registers =========
    float w0[32], w1[32];
    {
        const float* Wr0 = W + (size_t)(mi*64 + 2*lane)*NDIM;
        const float* Wr1 = Wr0 + NDIM;
        #pragma unroll
        for (int t = 0; t < 8; ++t) {
            const int k0 = t*64 + wid*4;
            const float4 a = *(const float4*)(Wr0 + k0);
            const float4 b = *(const float4*)(Wr1 + k0);
            w0[t*4+0] = rintf(a.x/scW)*scW; w0[t*4+1] = rintf(a.y/scW)*scW;
            w0[t*4+2] = rintf(a.z/scW)*scW; w0[t*4+3] = rintf(a.w/scW)*scW;
            w1[t*4+0] = rintf(b.x/scW)*scW; w1[t*4+1] = rintf(b.y/scW)*scW;
            w1[t*4+2] = rintf(b.z/scW)*scW; w1[t*4+3] = rintf(b.w/scW)*scW;
        }
    }

    // ================= z1 = relu(0.5*Ux): local own rows + publish + flag ==========
    {
        const float z1 = fmaxf(0.5f * sUx[tid], 0.f);
        sZ[(mi*64 + (tid>>3))*ZSTR + (tid&7)] = z1;
        __stcg(&g_zA[nj*4096 + mi*512 + tid], z1);
    }
    __syncthreads();
    if (tid == 0) {
        asm volatile("fence.acq_rel.gpu;" ::: "memory");
        flag_store(fown, base + 1u);
    }
    float* gz_cur = g_zA;
    float* gz_nxt = g_zB;

    // per-warp staging assignment: lane < 28 stages one remote row it will consume
    int st_row = -1;
    if (lane < 28) {
        int t = lane >> 2; t += (t >= mi);
        st_row = t*64 + wid*4 + (lane & 3);
    }
    // warp-0 polling assignment: lanes 0..6 poll the 7 remote flags
    const unsigned* fpoll = (lane < 7) ? (fg + (((mi + 1 + lane) & 7) * 32)) : fown;

    // ================= Main loop: 39 iterations (z2..z40) ==========================
    for (int it = 2; it <= ITERS; ++it) {
        ull a00=0,a01=0,a02=0,a03=0, a10=0,a11=0,a12=0,a13=0;

        // ---- own-tile GEMM first (local rows current; overlaps discovery) ----
        {
            const float* zt = sZ + (mi*64 + wid*4)*ZSTR;
            #pragma unroll
            for (int j2 = 0; j2 < 4; ++j2) {
                const float* q = zt + j2*ZSTR;
                const ulonglong2 zA = *(const ulonglong2*)(q);
                const ulonglong2 zB = *(const ulonglong2*)(q + 4);
                const ull wd0 = pk2(w0[mi*4+j2]);
                const ull wd1 = pk2(w1[mi*4+j2]);
                fma2(a00, wd0, zA.x); fma2(a01, wd0, zA.y);
                fma2(a02, wd0, zB.x); fma2(a03, wd0, zB.y);
                fma2(a10, wd1, zA.x); fma2(a11, wd1, zA.y);
                fma2(a12, wd1, zB.x); fma2(a13, wd1, zB.y);
            }
        }

        // ---- discovery: warp 0 lane-parallel acquire polls -> SMEM token ----
        const unsigned tgt = (unsigned)(it - 1);   // relative generation
        if (wid == 0) {
            if (lane < 7) {
                const unsigned abs_tgt = base + tgt;
                while ((int)(flag_acq(fpoll) - abs_tgt) < 0) { }
            }
            __syncwarp();
            if (lane == 0) tok_store(tok, tgt);
        } else {
            if (lane == 0) { while ((int)(tok_load(tok) - tgt) < 0) { } }
            __syncwarp();
        }

        // ---- per-warp stage of its own 28 remote rows ----
        if (lane < 28) {
            const float* src = gz_cur + nj*4096 + st_row*8;
            const float4 a = __ldcg((const float4*)src);
            const float4 b = __ldcg((const float4*)(src + 4));
            *(float4*)(sZ + st_row*ZSTR)     = a;
            *(float4*)(sZ + st_row*ZSTR + 4) = b;
        }
        __syncwarp();

        // ---- GEMM over the 7 remote tiles ----
        #pragma unroll
        for (int t = 0; t < 8; ++t) {
            if (t == mi) continue;
            const float* zt = sZ + (t*64 + wid*4)*ZSTR;
            #pragma unroll
            for (int j2 = 0; j2 < 4; ++j2) {
                const float* q = zt + j2*ZSTR;
                const ulonglong2 zA = *(const ulonglong2*)(q);
                const ulonglong2 zB = *(const ulonglong2*)(q + 4);
                const ull wd0 = pk2(w0[t*4+j2]);
                const ull wd1 = pk2(w1[t*4+j2]);
                fma2(a00, wd0, zA.x); fma2(a01, wd0, zA.y);
                fma2(a02, wd0, zB.x); fma2(a03, wd0, zB.y);
                fma2(a10, wd1, zA.x); fma2(a11, wd1, zA.y);
                fma2(a12, wd1, zB.x); fma2(a13, wd1, zB.y);
            }
        }

        // ---- partials: sRed[wid*640 + lane*20 + {0..15}] ----
        {
            float* rp = sRed + wid*640 + lane*20;
            ulonglong2 s0; s0.x = a00; s0.y = a01; *(ulonglong2*)(rp)      = s0;
            ulonglong2 s1; s1.x = a02; s1.y = a03; *(ulonglong2*)(rp + 4)  = s1;
            ulonglong2 s2; s2.x = a10; s2.y = a11; *(ulonglong2*)(rp + 8)  = s2;
            ulonglong2 s3; s3.x = a12; s3.y = a13; *(ulonglong2*)(rp + 12) = s3;
        }
        __syncthreads();

        // ---- combine + relu + publish + refresh local own row ----
        {
            const int coff = (tid >> 4)*20 + ((tid >> 3) & 1)*8 + (tid & 7);
            float s = 0.f;
            const float* rq = sRed + coff;
            #pragma unroll
            for (int q = 0; q < 16; ++q) s += rq[q*640];
            const int zidx = (mi*64 + (tid >> 3))*ZSTR + (tid & 7);
            const float u  = sUx[tid];
            const float zo = sZ[zidx];
            const float v  = fmaf(0.5f, zo, 0.5f * (s + u));
            const float zn = fmaxf(v, 0.f);
            __stcg(&gz_nxt[nj*4096 + mi*512 + tid], zn);
            sZ[zidx] = zn;
        }
        __syncthreads();
        if (tid == 0) {
            asm volatile("fence.acq_rel.gpu;" ::: "memory");
            flag_store(fown, base + (unsigned)it);
        }

        { float* t = gz_cur; gz_cur = gz_nxt; gz_nxt = t; }
    }

    // ================= Classifier (row-tile 0 CTA of each group) ====================
    if (mi == 0) {
        if (tid == 0) {
            const unsigned tgt = base + (unsigned)ITERS;
            for (;;) {
                int ok = 1;
                #pragma unroll
                for (int t = 1; t < 8; ++t)
                    ok &= ((int)(flag_ld(fg + t*32) - tgt) >= 0);
                if (ok) break;
            }
            asm volatile("fence.acq_rel.gpu;" ::: "memory");
        }
        __syncthreads();
        if (tid < 8*CDIM) {
            const int bl = tid / CDIM, cc = tid - bl*CDIM;
            const float* zp = gz_cur + nj*4096 + bl;
            const float* wc = Wc + cc*NDIM;
            float acc = bcv[cc];
            #pragma unroll 8
            for (int n = 0; n < NDIM; ++n)
                acc = fmaf(__ldcg(zp + n*8), wc[n], acc);
            out[(nj*8 + bl)*CDIM + cc] = acc;
        }
    }
}

extern "C" void kernel_launch(void* const* d_in, const int* in_sizes, int n_in,
                              void* d_out, int out_size) {
    (void)in_sizes; (void)n_in; (void)out_size;
    cudaFuncSetAttribute(mondeq_kernel, cudaFuncAttributeMaxDynamicSharedMemorySize, SMEM_BYTES);
    mondeq_kernel<<<GRID, TPB, SMEM_BYTES>>>(
        (const float*)d_in[0],   // W  (512,512)
        (const float*)d_in[1],   // U  (512,784)
        (const float*)d_in[2],   // b  (512)
        (const float*)d_in[3],   // x  (128,784)
        (const float*)d_in[4],   // Wc (10,512)
        (const float*)d_in[5],   // bc (10)
        (float*)d_out);          // logits (128,10)
}

// round 13
// speedup vs baseline: 2.2306x; 1.0083x over previous
#include <cuda_runtime.h>
#include <math.h>

typedef unsigned long long ull;

#define NDIM 512
#define DDIM 784
#define CDIM 10
#define ITERS 40
#define QMAX 127.0f

#define MT 8          // row tiles (64 rows each)
#define NT 16         // column groups (8 cols each)
#define GRID (MT*NT)  // 128 CTAs
#define TPB 512
#define ZSTR 12       // padded z row stride (8 used + 4 pad)

// shared layout (float offsets)
#define S_Z    0          // 512*12 = 6144 (single buffer, per-warp row ownership)
#define S_RED  6144       // 16 warps * 640 (lane*20: 16 floats + 4 pad) = 10240
#define S_UX   16384      // 512
#define S_TOK  16896      // token word
#define SMEM_FLOATS 16928
#define SMEM_BYTES (SMEM_FLOATS*4)
// Phase B scratch overlaps S_Z/S_RED: xs @0 (6272), uq @6272 (7424, ends 13696)

// ---- device globals (scratch) ----
__device__ float g_zA[NDIM*128];
__device__ float g_zB[NDIM*128];
__device__ unsigned g_maxW, g_maxU, g_maxB;        // idempotent atomicMax
__device__ unsigned g_gcnt, g_ggen;                // grid barrier (used once)
__device__ unsigned g_flag[NT*8*32];               // per-CTA flags, 128B apart

// -------- grid barrier (prologue only) --------
__device__ __forceinline__ void gbar(unsigned* cnt, unsigned* gen, unsigned expected) {
    __syncthreads();
    if (threadIdx.x == 0) {
        unsigned snap, t;
        asm volatile("ld.acquire.gpu.global.u32 %0, [%1];" : "=r"(snap) : "l"(gen) : "memory");
        asm volatile("atom.acq_rel.gpu.global.add.u32 %0, [%1], %2;"
                     : "=r"(t) : "l"(cnt), "r"(1u) : "memory");
        if (t == expected - 1u) {
            asm volatile("st.relaxed.gpu.global.u32 [%0], %1;" :: "l"(cnt), "r"(0u) : "memory");
            asm volatile("red.release.gpu.global.add.u32 [%0], %1;" :: "l"(gen), "r"(1u) : "memory");
        } else {
            unsigned g;
            do {
                asm volatile("ld.acquire.gpu.global.u32 %0, [%1];" : "=r"(g) : "l"(gen) : "memory");
            } while (g == snap);
        }
    }
    __syncthreads();
}

// -------- flag / token / barrier primitives --------
__device__ __forceinline__ void flag_store(unsigned* f, unsigned v) {
    asm volatile("st.release.gpu.global.u32 [%0], %1;" :: "l"(f), "r"(v) : "memory");
}
__device__ __forceinline__ unsigned flag_ld(const unsigned* f) {
    unsigned v;
    asm volatile("ld.relaxed.gpu.global.u32 %0, [%1];" : "=r"(v) : "l"(f) : "memory");
    return v;
}
__device__ __forceinline__ unsigned flag_acq(const unsigned* f) {
    unsigned v;
    asm volatile("ld.acquire.gpu.global.u32 %0, [%1];" : "=r"(v) : "l"(f) : "memory");
    return v;
}
__device__ __forceinline__ unsigned smem_u32(const void* p){
    unsigned r; asm("{.reg .u64 t; cvta.to.shared.u64 t, %1; cvt.u32.u64 %0, t;}" : "=r"(r) : "l"(p)); return r;
}
__device__ __forceinline__ void tok_store(unsigned a, unsigned v){
    asm volatile("st.release.cta.shared.u32 [%0], %1;" :: "r"(a), "r"(v) : "memory");
}
__device__ __forceinline__ unsigned tok_load(unsigned a){
    unsigned v;
    asm volatile("ld.acquire.cta.shared.u32 %0, [%1];" : "=r"(v) : "r"(a) : "memory");
    return v;
}
__device__ __forceinline__ void bar_arrive1(){
    asm volatile("bar.arrive 1, %0;" :: "r"(TPB) : "memory");
}
__device__ __forceinline__ void bar_sync1(){
    asm volatile("bar.sync 1, %0;" :: "r"(TPB) : "memory");
}

// -------- f32x2 helpers --------
__device__ __forceinline__ ull pk2(float x){
    ull d; asm("mov.b64 %0, {%1,%1};" : "=l"(d) : "r"(__float_as_uint(x))); return d;
}
__device__ __forceinline__ void fma2(ull& d, ull a, ull b){
    asm("fma.rn.f32x2 %0, %1, %2, %3;" : "=l"(d) : "l"(a), "l"(b), "l"(d));
}
__device__ __forceinline__ float warpmax(float v){
    #pragma unroll
    for (int o = 16; o; o >>= 1) v = fmaxf(v, __shfl_xor_sync(0xffffffffu, v, o));
    return v;
}

extern "C" __global__ void __launch_bounds__(TPB, 1)
mondeq_kernel(const float* __restrict__ W, const float* __restrict__ U,
              const float* __restrict__ bvec, const float* __restrict__ x,
              const float* __restrict__ Wc, const float* __restrict__ bcv,
              float* __restrict__ out)
{
    extern __shared__ float sm[];
    float* sZ   = sm + S_Z;
    float* sRed = sm + S_RED;
    float* sUx  = sm + S_UX;

    const int tid  = threadIdx.x;
    const int cta  = blockIdx.x;
    const int mi   = cta & (MT - 1);   // row tile 0..7
    const int nj   = cta >> 3;         // column group 0..15
    const int wid  = tid >> 5;         // warp: k within tile = wid*4 + j2
    const int lane = tid & 31;         // rows 2*lane, 2*lane+1 of own tile
    unsigned* fg   = &g_flag[nj*8*32]; // group flag base
    unsigned* fown = fg + mi*32;
    const unsigned tok = smem_u32(sm) + S_TOK*4;

    // base generation (own flag written only by this CTA; stable at launch)
    unsigned base = 0u;
    if (tid == 0) base = flag_ld(fown);

    // ================= Phase A: per-tensor max|.| (idempotent atomicMax) ==========
    {
        float lw = 0.f, lu = 0.f, lb = 0.f;
        const int gid = cta * TPB + tid;
        for (int i = gid; i < NDIM*NDIM; i += GRID*TPB) lw = fmaxf(lw, fabsf(W[i]));
        for (int i = gid; i < NDIM*DDIM; i += GRID*TPB) lu = fmaxf(lu, fabsf(U[i]));
        if (gid < NDIM) lb = fabsf(bvec[gid]);
        lw = warpmax(lw); lu = warpmax(lu); lb = warpmax(lb);
        if (lane == 0) { sm[wid] = lw; sm[16 + wid] = lu; sm[32 + wid] = lb; }
        __syncthreads();
        if (tid == 0) {
            float mw = 0.f, mu = 0.f, mb = 0.f;
            #pragma unroll
            for (int i = 0; i < 16; ++i) {
                mw = fmaxf(mw, sm[i]); mu = fmaxf(mu, sm[16+i]); mb = fmaxf(mb, sm[32+i]);
            }
            atomicMax(&g_maxW, __float_as_uint(mw));
            atomicMax(&g_maxU, __float_as_uint(mu));
            atomicMax(&g_maxB, __float_as_uint(mb));
            ((unsigned*)sm)[S_TOK] = 0u;    // token init
        }
    }
    gbar(&g_gcnt, &g_ggen, GRID);   // the ONLY grid barrier

    const float scW = __uint_as_float(__ldcg(&g_maxW)) / QMAX;
    const float scU = __uint_as_float(__ldcg(&g_maxU)) / QMAX;
    const float scB = __uint_as_float(__ldcg(&g_maxB)) / QMAX;

    // ================= Phase B (group-local): Ux = Uq @ x^T + bq ===================
    {
        float* xs = sm;            // [784][8] transposed x cols (6272)
        float* uq = sm + 6272;     // [64][116] quantized U chunk (7424)
        const int r = tid >> 3;
        const int c = tid & 7;
        for (int i = tid; i < DDIM*8; i += TPB) {
            const int k = i >> 3, cc = i & 7;
            xs[i] = x[(size_t)(nj*8 + cc)*DDIM + k];
        }
        float acc = 0.f;
        for (int ch = 0; ch < 7; ++ch) {
            __syncthreads();
            for (int i = tid; i < 64*112; i += TPB) {
                const int rr = i / 112, kk = i - rr*112;
                uq[rr*116 + kk] = rintf(U[(size_t)(mi*64 + rr)*DDIM + ch*112 + kk] / scU) * scU;
            }
            __syncthreads();
            const float* up = uq + r*116;
            const float* xp = xs + ch*112*8 + c;
            #pragma unroll 4
            for (int kk = 0; kk < 112; ++kk)
                acc = fmaf(up[kk], xp[kk*8], acc);
        }
        const float bq = rintf(bvec[mi*64 + r] / scB) * scB;
        __syncthreads();                 // uq/xs reads done before sZ/sRed reuse
        sUx[tid] = acc + bq;
    }

    // ================= Phase C: quantized W -> per-thread scalar registers =========
    float w0[32], w1[32];
    {
        const float* Wr0 = W + (size_t)(mi*64 + 2*lane)*NDIM;
        const float* Wr1 = Wr0 + NDIM;
        #pragma unroll
        for (int t = 0; t < 8; ++t) {
            const int k0 = t*64 + wid*4;
            const float4 a = *(const float4*)(Wr0 + k0);
            const float4 b = *(const float4*)(Wr1 + k0);
            w0[t*4+0] = rintf(a.x/scW)*scW; w0[t*4+1] = rintf(a.y/scW)*scW;
            w0[t*4+2] = rintf(a.z/scW)*scW; w0[t*4+3] = rintf(a.w/scW)*scW;
            w1[t*4+0] = rintf(b.x/scW)*scW; w1[t*4+1] = rintf(b.y/scW)*scW;
            w1[t*4+2] = rintf(b.z/scW)*scW; w1[t*4+3] = rintf(b.w/scW)*scW;
        }
    }

    // ================= z1 = relu(0.5*Ux): local own rows + publish + flag ==========
    {
        const float z1 = fmaxf(0.5f * sUx[tid], 0.f);
        sZ[(mi*64 + (tid>>3))*ZSTR + (tid&7)] = z1;
        __stcg(&g_zA[nj*4096 + mi*512 + tid], z1);
    }
    __syncthreads();
    if (tid == 0) {
        asm volatile("fence.acq_rel.gpu;" ::: "memory");
        flag_store(fown, base + 1u);
    }
    float* gz_cur = g_zA;
    float* gz_nxt = g_zB;

    // per-warp staging assignment: lane < 28 stages one remote row it will consume
    int st_row = -1;
    if (lane < 28) {
        int t = lane >> 2; t += (t >= mi);
        st_row = t*64 + wid*4 + (lane & 3);
    }
    // warp-0 polling assignment: lanes 0..6 poll the 7 remote flags
    const unsigned* fpoll = (lane < 7) ? (fg + (((mi + 1 + lane) & 7) * 32)) : fown;

    // ================= Main loop: 39 iterations (z2..z40) ==========================
    for (int it = 2; it <= ITERS; ++it) {
        ull a00=0,a01=0,a02=0,a03=0, a10=0,a11=0,a12=0,a13=0;

        // ---- own-tile GEMM first (rows wid*4..+3 written by THIS warp's combine) --
        {
            const float* zt = sZ + (mi*64 + wid*4)*ZSTR;
            #pragma unroll
            for (int j2 = 0; j2 < 4; ++j2) {
                const float* q = zt + j2*ZSTR;
                const ulonglong2 zA = *(const ulonglong2*)(q);
                const ulonglong2 zB = *(const ulonglong2*)(q + 4);
                const ull wd0 = pk2(w0[mi*4+j2]);
                const ull wd1 = pk2(w1[mi*4+j2]);
                fma2(a00, wd0, zA.x); fma2(a01, wd0, zA.y);
                fma2(a02, wd0, zB.x); fma2(a03, wd0, zB.y);
                fma2(a10, wd1, zA.x); fma2(a11, wd1, zA.y);
                fma2(a12, wd1, zB.x); fma2(a13, wd1, zB.y);
            }
        }

        // ---- discovery: warp 0 lane-parallel acquire polls -> SMEM token ----
        const unsigned tgt = (unsigned)(it - 1);   // relative generation
        if (wid == 0) {
            if (lane < 7) {
                const unsigned abs_tgt = base + tgt;
                while ((int)(flag_acq(fpoll) - abs_tgt) < 0) { }
            }
            __syncwarp();
            if (lane == 0) tok_store(tok, tgt);
        } else {
            if (lane == 0) { while ((int)(tok_load(tok) - tgt) < 0) { } }
            __syncwarp();
        }

        // ---- per-warp stage of its own 28 remote rows ----
        if (lane < 28) {
            const float* src = gz_cur + nj*4096 + st_row*8;
            const float4 a = __ldcg((const float4*)src);
            const float4 b = __ldcg((const float4*)(src + 4));
            *(float4*)(sZ + st_row*ZSTR)     = a;
            *(float4*)(sZ + st_row*ZSTR + 4) = b;
        }
        __syncwarp();

        // ---- GEMM over the 7 remote tiles ----
        #pragma unroll
        for (int t = 0; t < 8; ++t) {
            if (t == mi) continue;
            const float* zt = sZ + (t*64 + wid*4)*ZSTR;
            #pragma unroll
            for (int j2 = 0; j2 < 4; ++j2) {
                const float* q = zt + j2*ZSTR;
                const ulonglong2 zA = *(const ulonglong2*)(q);
                const ulonglong2 zB = *(const ulonglong2*)(q + 4);
                const ull wd0 = pk2(w0[t*4+j2]);
                const ull wd1 = pk2(w1[t*4+j2]);
                fma2(a00, wd0, zA.x); fma2(a01, wd0, zA.y);
                fma2(a02, wd0, zB.x); fma2(a03, wd0, zB.y);
                fma2(a10, wd1, zA.x); fma2(a11, wd1, zA.y);
                fma2(a12, wd1, zB.x); fma2(a13, wd1, zB.y);
            }
        }

        // ---- partials: sRed[wid*640 + lane*20 + {0..15}] ----
        {
            float* rp = sRed + wid*640 + lane*20;
            ulonglong2 s0; s0.x = a00; s0.y = a01; *(ulonglong2*)(rp)      = s0;
            ulonglong2 s1; s1.x = a02; s1.y = a03; *(ulonglong2*)(rp + 4)  = s1;
            ulonglong2 s2; s2.x = a10; s2.y = a11; *(ulonglong2*)(rp + 8)  = s2;
            ulonglong2 s3; s3.x = a12; s3.y = a13; *(ulonglong2*)(rp + 12) = s3;
        }
        __syncthreads();   // all partials visible for combine

        // ---- combine + relu + publish + refresh local own row (warp-local) ----
        {
            const int coff = (tid >> 4)*20 + ((tid >> 3) & 1)*8 + (tid & 7);
            float s = 0.f;
            const float* rq = sRed + coff;
            #pragma unroll
            for (int q = 0; q < 16; ++q) s += rq[q*640];
            const int zidx = (mi*64 + (tid >> 3))*ZSTR + (tid & 7);
            const float u  = sUx[tid];
            const float zo = sZ[zidx];
            const float v  = fmaf(0.5f, zo, 0.5f * (s + u));
            const float zn = fmaxf(v, 0.f);
            __stcg(&gz_nxt[nj*4096 + mi*512 + tid], zn);
            sZ[zidx] = zn;
        }
        __syncwarp();      // own-row sZ writes visible within warp (ownGEMM next iter)

        // ---- decoupled publish: workers arrive & run ahead; warp 0 joins + flags ---
        if (wid == 0) {
            bar_sync1();                       // all warps' combine (incl. STGs) done
            if (lane == 0) {
                asm volatile("fence.acq_rel.gpu;" ::: "memory");
                flag_store(fown, base + (unsigned)it);
            }
        } else {
            bar_arrive1();                     // non-blocking; slide into next iter
        }

        { float* t = gz_cur; gz_cur = gz_nxt; gz_nxt = t; }
    }

    __syncthreads();   // join all warps; own-CTA z40 STGs ordered before reads below

    // ================= Classifier (row-tile 0 CTA of each group) ====================
    if (mi == 0) {
        if (tid == 0) {
            const unsigned tgt = base + (unsigned)ITERS;
            for (;;) {
                int ok = 1;
                #pragma unroll
                for (int t = 1; t < 8; ++t)
                    ok &= ((int)(flag_ld(fg + t*32) - tgt) >= 0);
                if (ok) break;
            }
            asm volatile("fence.acq_rel.gpu;" ::: "memory");
        }
        __syncthreads();
        if (tid < 8*CDIM) {
            const int bl = tid / CDIM, cc = tid - bl*CDIM;
            const float* zp = gz_cur + nj*4096 + bl;
            const float* wc = Wc + cc*NDIM;
            float acc = bcv[cc];
            #pragma unroll 8
            for (int n = 0; n < NDIM; ++n)
                acc = fmaf(__ldcg(zp + n*8), wc[n], acc);
            out[(nj*8 + bl)*CDIM + cc] = acc;
        }
    }
}

extern "C" void kernel_launch(void* const* d_in, const int* in_sizes, int n_in,
                              void* d_out, int out_size) {
    (void)in_sizes; (void)n_in; (void)out_size;
    cudaFuncSetAttribute(mondeq_kernel, cudaFuncAttributeMaxDynamicSharedMemorySize, SMEM_BYTES);
    mondeq_kernel<<<GRID, TPB, SMEM_BYTES>>>(
        (const float*)d_in[0],   // W  (512,512)
        (const float*)d_in[1],   // U  (512,784)
        (const float*)d_in[2],   // b  (512)
        (const float*)d_in[3],   // x  (128,784)
        (const float*)d_in[4],   // Wc (10,512)
        (const float*)d_in[5],   // bc (10)
        (float*)d_out);          // logits (128,10)
}